// round 8
// baseline (speedup 1.0000x reference)
#include <cuda_runtime.h>
#include <math.h>

// Problem constants
#define BB   32
#define SS   1024
#define DD   3
#define NF   512
#define NS   64
#define HID  100
#define FSZ  256

// Decomposition
#define NSC  16           // S chunks
#define SCH  (SS/NSC)     // 64 steps per chunk
#define G    4            // fourier samples per MLP block

// Scratch (device globals: allocation-free per harness rules)
__device__ float g_Womg[NF*3];
__device__ float g_totC[BB*NSC*NF];
__device__ float g_totS[BB*NSC*NF];

// Warp-wide float add reduction (SHFL butterfly; redux.f32 unavailable on
// the compute_103 PTX target).
__device__ __forceinline__ float warp_sum(float v) {
    #pragma unroll
    for (int o = 16; o; o >>= 1) v += __shfl_xor_sync(0xffffffffu, v, o);
    return v;
}

// ---------------- Fused Fourier-feature MLP ----------------
// G=4 fourier samples per block (128 blocks x 128 threads): W2 is streamed
// once per block for 4 samples -> 4x less L2 traffic, 4x FMA per load.

__global__ void __launch_bounds__(128) k_mlp(const float* __restrict__ noise,
                                             const float* __restrict__ W1,
                                             const float* __restrict__ b1,
                                             const float* __restrict__ W2,
                                             const float* __restrict__ b2,
                                             const float* __restrict__ W) {
    int f0 = blockIdx.x * G;
    int t  = threadIdx.x;

    __shared__ float s_noise[G][NS];
    __shared__ float s_h[G][HID];
    __shared__ float s_red[G][4][3];

    for (int i = t; i < G*NS; i += 128)
        s_noise[i/NS][i%NS] = noise[f0*NS + i];
    __syncthreads();

    // hidden: G*HID = 400 dot products of length 64
    for (int idx = t; idx < G*HID; idx += 128) {
        int fl = idx / HID, j = idx % HID;
        float acc = b1[j];
        #pragma unroll 8
        for (int k = 0; k < NS; k++)
            acc = fmaf(s_noise[fl][k], W1[k*HID + j], acc);
        s_h[fl][j] = tanhf(acc);
    }
    __syncthreads();

    // fourier + Womg: thread owns columns i0=t, i1=t+128 for all G samples
    int i0 = t, i1 = t + 128;
    float a0[G], a1[G];
    {
        float bb0 = b2[i0], bb1 = b2[i1];
        #pragma unroll
        for (int fl = 0; fl < G; fl++) { a0[fl] = bb0; a1[fl] = bb1; }
    }
    for (int j = 0; j < HID; j++) {
        float wa = W2[j*FSZ + i0], wb = W2[j*FSZ + i1];
        #pragma unroll
        for (int fl = 0; fl < G; fl++) {
            a0[fl] = fmaf(s_h[fl][j], wa, a0[fl]);
            a1[fl] = fmaf(s_h[fl][j], wb, a1[fl]);
        }
    }

    float Wa0 = W[i0*3+0], Wa1 = W[i0*3+1], Wa2 = W[i0*3+2];
    float Wb0 = W[i1*3+0], Wb1 = W[i1*3+1], Wb2 = W[i1*3+2];
    int lane = t & 31, warp = t >> 5;
    #pragma unroll
    for (int fl = 0; fl < G; fl++) {
        float fs0 = tanhf(a0[fl]), fs1 = tanhf(a1[fl]);
        float p0 = fmaf(fs0, Wa0, fs1*Wb0);
        float p1 = fmaf(fs0, Wa1, fs1*Wb1);
        float p2 = fmaf(fs0, Wa2, fs1*Wb2);
        p0 = warp_sum(p0); p1 = warp_sum(p1); p2 = warp_sum(p2);
        if (lane == 0) {
            s_red[fl][warp][0] = p0;
            s_red[fl][warp][1] = p1;
            s_red[fl][warp][2] = p2;
        }
    }
    __syncthreads();
    if (t < G*3) {
        int fl = t / 3, d = t % 3;
        float v = s_red[fl][0][d] + s_red[fl][1][d]
                + s_red[fl][2][d] + s_red[fl][3][d];
        g_Womg[(f0 + fl)*3 + d] = v;
    }
}

// ---------------- Pass A: per-S-chunk trig totals ----------------
// 512 threads = all NF features; grid (NSC, BB).

__global__ void __launch_bounds__(512) k_passA(const float* __restrict__ X) {
    int t  = threadIdx.x;            // n = t
    int sc = blockIdx.x, b = blockIdx.y;
    float w0 = g_Womg[t*3+0], w1 = g_Womg[t*3+1], w2 = g_Womg[t*3+2];

    __shared__ float sx[SCH*3];
    int s0 = sc*SCH;
    const float* xp = X + ((size_t)b*SS + s0)*3;
    if (t < SCH*3) sx[t] = xp[t];
    __syncthreads();

    float sumC = 0.f, sumS = 0.f;
    #pragma unroll 8
    for (int k = 0; k < SCH; k++) {
        float th = fmaf(sx[k*3+2], w2, fmaf(sx[k*3+1], w1, sx[k*3]*w0));
        float sv, cv;
        __sincosf(th, &sv, &cv);
        sumC += cv; sumS += sv;
    }
    g_totC[(b*NSC + sc)*NF + t] = sumC;
    g_totS[(b*NSC + sc)*NF + t] = sumS;
}

// ---------------- Pass C fused with final output ----------------
// Same grid/block as passA. All 16 warp-partials per step stay in smem;
// block reduces them and writes lam + loglik directly.

__global__ void __launch_bounds__(512) k_passCF(const float* __restrict__ X,
                                                const float* __restrict__ alpha,
                                                float* __restrict__ out) {
    int t  = threadIdx.x;            // n = t
    int sc = blockIdx.x, b = blockIdx.y;
    float w0 = g_Womg[t*3+0], w1 = g_Womg[t*3+1], w2 = g_Womg[t*3+2];

    // exclusive offsets from preceding S chunks
    float runC = 0.f, runS = 0.f;
    for (int p = 0; p < sc; p++) {
        runC += g_totC[(b*NSC + p)*NF + t];
        runS += g_totS[(b*NSC + p)*NF + t];
    }

    __shared__ float sx[SCH*3];
    __shared__ float s_red[SCH][17];   // +1 pad: conflict-free tail reads
    int s0 = sc*SCH;
    const float* xp = X + ((size_t)b*SS + s0)*3;
    if (t < SCH*3) sx[t] = xp[t];
    __syncthreads();

    int lane = t & 31, warp = t >> 5;

    #pragma unroll 4
    for (int k = 0; k < SCH; k++) {
        float th = fmaf(sx[k*3+2], w2, fmaf(sx[k*3+1], w1, sx[k*3]*w0));
        float sv, cv;
        __sincosf(th, &sv, &cv);
        float contrib = cv*runC + sv*runS;   // EXCLUSIVE prefix
        runC += cv; runS += sv;
        contrib = warp_sum(contrib);
        if (lane == 0) s_red[k][warp] = contrib;
    }
    __syncthreads();

    if (t < SCH) {
        float s = 0.f;
        #pragma unroll
        for (int i = 0; i < 16; i++) s += s_red[t][i];
        float lam = fmaf(alpha[0], s * (1.0f/NF), 10.0f);
        int sg = s0 + t;
        out[b*SS + sg] = lam;

        float x0 = sx[t*3];
        float mask = (x0 > 0.f) ? 1.f : 0.f;
        const float C2 = -3947.8417604357433f;   // -MU*T*(2*pi)^(D-1)
        out[BB*SS + b*(SS+1) + sg] = logf(lam)*mask + C2;
    }
    if (sc == 0 && t == 0) {
        const float C2 = -3947.8417604357433f;
        out[BB*SS + b*(SS+1) + SS] = C2;         // extra (S+1)-th column
    }
}

// ---------------- Launch ----------------

extern "C" void kernel_launch(void* const* d_in, const int* in_sizes, int n_in,
                              void* d_out, int out_size) {
    const float* X     = (const float*)d_in[0];
    const float* noise = (const float*)d_in[1];
    const float* W1    = (const float*)d_in[2];
    const float* b1    = (const float*)d_in[3];
    const float* W2    = (const float*)d_in[4];
    const float* b2    = (const float*)d_in[5];
    const float* W     = (const float*)d_in[6];
    const float* alpha = (const float*)d_in[7];
    float* out = (float*)d_out;

    k_mlp<<<NF/G, 128>>>(noise, W1, b1, W2, b2, W);

    dim3 grid(NSC, BB);
    k_passA <<<grid, 512>>>(X);
    k_passCF<<<grid, 512>>>(X, alpha, out);
}

// round 9
// speedup vs baseline: 1.1951x; 1.1951x over previous
#include <cuda_runtime.h>
#include <math.h>

// Problem constants
#define BB   32
#define SS   1024
#define DD   3
#define NF   512
#define NS   64
#define HID  100
#define FSZ  256

// Decomposition
#define NSC  16           // S chunks
#define SCH  (SS/NSC)     // 64 steps per chunk

// Scratch (device globals: allocation-free per harness rules)
__device__ float g_Womg[NF*3];
__device__ float g_totC[BB*NSC*NF];
__device__ float g_totS[BB*NSC*NF];

// Warp-wide float add reduction (SHFL butterfly; redux.f32 unavailable on
// the compute_103 PTX target).
__device__ __forceinline__ float warp_sum(float v) {
    #pragma unroll
    for (int o = 16; o; o >>= 1) v += __shfl_xor_sync(0xffffffffu, v, o);
    return v;
}

// ---------------- Fused Fourier-feature MLP ----------------
// One block per fourier sample f (512 blocks x 256 threads = ~27 warps/SM).
// Thread t owns fourier column i = t. W2 loads are coalesced and L1/L2
// resident; j-loop unrolled x4 for MLP. The whole MLP is latency-, not
// bandwidth-, limited, so parallelism is the lever.

__global__ void __launch_bounds__(256) k_mlp(const float* __restrict__ noise,
                                             const float* __restrict__ W1,
                                             const float* __restrict__ b1,
                                             const float* __restrict__ W2,
                                             const float* __restrict__ b2,
                                             const float* __restrict__ W) {
    int f = blockIdx.x;
    int t = threadIdx.x;

    __shared__ float s_noise[NS];
    __shared__ float s_h[HID];
    __shared__ float s_red[8][3];

    if (t < NS) s_noise[t] = noise[f*NS + t];
    __syncthreads();

    // hidden: h[j] = tanh(b1[j] + sum_k noise[k] * W1[k,j])  (threads 0..99)
    if (t < HID) {
        float acc = b1[t];
        #pragma unroll 8
        for (int k = 0; k < NS; k++)
            acc = fmaf(s_noise[k], W1[k*HID + t], acc);
        s_h[t] = tanhf(acc);
    }
    __syncthreads();

    // fourier column t: fs = tanh(b2[t] + sum_j h[j] * W2[j,t])
    float acc = b2[t];
    #pragma unroll 4
    for (int j = 0; j < HID; j += 4) {
        float a0 = fmaf(s_h[j+0], W2[(j+0)*FSZ + t], 0.f);
        float a1 = fmaf(s_h[j+1], W2[(j+1)*FSZ + t], 0.f);
        float a2 = fmaf(s_h[j+2], W2[(j+2)*FSZ + t], 0.f);
        float a3 = fmaf(s_h[j+3], W2[(j+3)*FSZ + t], 0.f);
        acc += (a0 + a1) + (a2 + a3);
    }
    float fs = tanhf(acc);

    // Womg[f][d] = sum_i fs[i] * W[i,d]
    float p0 = fs * W[t*3+0];
    float p1 = fs * W[t*3+1];
    float p2 = fs * W[t*3+2];
    p0 = warp_sum(p0); p1 = warp_sum(p1); p2 = warp_sum(p2);
    int lane = t & 31, warp = t >> 5;
    if (lane == 0) { s_red[warp][0] = p0; s_red[warp][1] = p1; s_red[warp][2] = p2; }
    __syncthreads();
    if (t < 3) {
        float v = 0.f;
        #pragma unroll
        for (int w = 0; w < 8; w++) v += s_red[w][t];
        g_Womg[f*3 + t] = v;
    }
}

// ---------------- Pass A: per-S-chunk trig totals ----------------
// 512 threads = all NF features; grid (NSC, BB).

__global__ void __launch_bounds__(512) k_passA(const float* __restrict__ X) {
    int t  = threadIdx.x;            // n = t
    int sc = blockIdx.x, b = blockIdx.y;
    float w0 = g_Womg[t*3+0], w1 = g_Womg[t*3+1], w2 = g_Womg[t*3+2];

    __shared__ float sx[SCH*3];
    int s0 = sc*SCH;
    const float* xp = X + ((size_t)b*SS + s0)*3;
    if (t < SCH*3) sx[t] = xp[t];
    __syncthreads();

    float sumC = 0.f, sumS = 0.f;
    #pragma unroll 8
    for (int k = 0; k < SCH; k++) {
        float th = fmaf(sx[k*3+2], w2, fmaf(sx[k*3+1], w1, sx[k*3]*w0));
        float sv, cv;
        __sincosf(th, &sv, &cv);
        sumC += cv; sumS += sv;
    }
    g_totC[(b*NSC + sc)*NF + t] = sumC;
    g_totS[(b*NSC + sc)*NF + t] = sumS;
}

// ---------------- Pass C fused with final output ----------------
// Same grid/block as passA. All 16 warp-partials per step stay in smem;
// block reduces them and writes lam + loglik directly.

__global__ void __launch_bounds__(512) k_passCF(const float* __restrict__ X,
                                                const float* __restrict__ alpha,
                                                float* __restrict__ out) {
    int t  = threadIdx.x;            // n = t
    int sc = blockIdx.x, b = blockIdx.y;
    float w0 = g_Womg[t*3+0], w1 = g_Womg[t*3+1], w2 = g_Womg[t*3+2];

    // exclusive offsets from preceding S chunks
    float runC = 0.f, runS = 0.f;
    for (int p = 0; p < sc; p++) {
        runC += g_totC[(b*NSC + p)*NF + t];
        runS += g_totS[(b*NSC + p)*NF + t];
    }

    __shared__ float sx[SCH*3];
    __shared__ float s_red[SCH][17];   // +1 pad: conflict-free tail reads
    int s0 = sc*SCH;
    const float* xp = X + ((size_t)b*SS + s0)*3;
    if (t < SCH*3) sx[t] = xp[t];
    __syncthreads();

    int lane = t & 31, warp = t >> 5;

    #pragma unroll 4
    for (int k = 0; k < SCH; k++) {
        float th = fmaf(sx[k*3+2], w2, fmaf(sx[k*3+1], w1, sx[k*3]*w0));
        float sv, cv;
        __sincosf(th, &sv, &cv);
        float contrib = cv*runC + sv*runS;   // EXCLUSIVE prefix
        runC += cv; runS += sv;
        contrib = warp_sum(contrib);
        if (lane == 0) s_red[k][warp] = contrib;
    }
    __syncthreads();

    if (t < SCH) {
        float s = 0.f;
        #pragma unroll
        for (int i = 0; i < 16; i++) s += s_red[t][i];
        float lam = fmaf(alpha[0], s * (1.0f/NF), 10.0f);
        int sg = s0 + t;
        out[b*SS + sg] = lam;

        float x0 = sx[t*3];
        float mask = (x0 > 0.f) ? 1.f : 0.f;
        const float C2 = -3947.8417604357433f;   // -MU*T*(2*pi)^(D-1)
        out[BB*SS + b*(SS+1) + sg] = logf(lam)*mask + C2;
    }
    if (sc == 0 && t == 0) {
        const float C2 = -3947.8417604357433f;
        out[BB*SS + b*(SS+1) + SS] = C2;         // extra (S+1)-th column
    }
}

// ---------------- Launch ----------------

extern "C" void kernel_launch(void* const* d_in, const int* in_sizes, int n_in,
                              void* d_out, int out_size) {
    const float* X     = (const float*)d_in[0];
    const float* noise = (const float*)d_in[1];
    const float* W1    = (const float*)d_in[2];
    const float* b1    = (const float*)d_in[3];
    const float* W2    = (const float*)d_in[4];
    const float* b2    = (const float*)d_in[5];
    const float* W     = (const float*)d_in[6];
    const float* alpha = (const float*)d_in[7];
    float* out = (float*)d_out;

    k_mlp<<<NF, 256>>>(noise, W1, b1, W2, b2, W);

    dim3 grid(NSC, BB);
    k_passA <<<grid, 512>>>(X);
    k_passCF<<<grid, 512>>>(X, alpha, out);
}